// round 14
// baseline (speedup 1.0000x reference)
#include <cuda_runtime.h>

// GridPooling: scatter-max of 500K x 128 fp32 features into a 32x32x32 grid,
// clamped at 0. Strategy:
//   1) zero-init output (harness poisons it to 0xAA)
//   2) one warp per point; each lane handles 4 features via float4;
//      skip v<=0 (cannot affect max(.,0) with 0-init), atomicMax on int bits
//      (exact for positive floats).

#define GP_F 128
#define GP_W 32
#define GP_H 32
#define GP_D 32
#define GP_CELLS (GP_W * GP_H * GP_D)

__global__ void gp_zero_kernel(float4* __restrict__ out, int n4) {
    int i = blockIdx.x * blockDim.x + threadIdx.x;
    if (i < n4) out[i] = make_float4(0.f, 0.f, 0.f, 0.f);
}

__global__ __launch_bounds__(256) void gp_scatter_max_kernel(
    const float4* __restrict__ feats4,   // [N, 32] float4 view of [N,128]
    const float*  __restrict__ pts,      // [N, 3]
    int*          __restrict__ out,      // [CELLS, 128] as int bits, zero-inited
    int N)
{
    int gtid = blockIdx.x * blockDim.x + threadIdx.x;
    int p    = gtid >> 5;        // one warp per point
    int lane = gtid & 31;
    if (p >= N) return;

    // Voxel index (all lanes load same 3 words -> L1 broadcast)
    float x = pts[p * 3 + 0];
    float y = pts[p * 3 + 1];
    float z = pts[p * 3 + 2];
    int ix = min(max(__float2int_rd(x * (float)GP_W), 0), GP_W - 1);
    int iy = min(max(__float2int_rd(y * (float)GP_H), 0), GP_H - 1);
    int iz = min(max(__float2int_rd(z * (float)GP_D), 0), GP_D - 1);
    int cell = ix * (GP_H * GP_D) + iy * GP_D + iz;

    // Coalesced 512B feature read per point
    float4 v = feats4[(size_t)p * (GP_F / 4) + lane];

    int* o = out + (size_t)cell * GP_F + lane * 4;
    // Positive floats compare identically as ints; v<=0 can never beat the
    // 0-initialized output, so skip those atomics entirely.
    if (v.x > 0.f) atomicMax(o + 0, __float_as_int(v.x));
    if (v.y > 0.f) atomicMax(o + 1, __float_as_int(v.y));
    if (v.z > 0.f) atomicMax(o + 2, __float_as_int(v.z));
    if (v.w > 0.f) atomicMax(o + 3, __float_as_int(v.w));
}

extern "C" void kernel_launch(void* const* d_in, const int* in_sizes, int n_in,
                              void* d_out, int out_size) {
    const float* feats = (const float*)d_in[0];   // [N,128]
    const float* pts   = (const float*)d_in[1];   // [N,3]
    float* out = (float*)d_out;                   // [32768,128]

    int N = in_sizes[0] / GP_F;

    // 1) zero-init output: 32768*128 = 4,194,304 floats = 1,048,576 float4
    int n4 = (GP_CELLS * GP_F) / 4;
    gp_zero_kernel<<<(n4 + 255) / 256, 256>>>((float4*)out, n4);

    // 2) scatter-max: one warp per point
    long long total_threads = (long long)N * 32;
    int blocks = (int)((total_threads + 255) / 256);
    gp_scatter_max_kernel<<<blocks, 256>>>(
        (const float4*)feats, pts, (int*)out, N);
}